// round 4
// baseline (speedup 1.0000x reference)
#include <cuda_runtime.h>
#include <math.h>

// ---------------------------------------------------------------------------
// Problem constants
// ---------------------------------------------------------------------------
#define D_MODEL 2048
#define N_HEADS 16
#define D_KH    128
#define D_FF    5504
#define BATCH   2
#define SEQ     2048
#define ROWS    (BATCH * SEQ)

// ---------------------------------------------------------------------------
// Scratch (device globals: allocation-free, capture-safe)
// ---------------------------------------------------------------------------
__device__ float g_xn   [ROWS * (size_t)D_MODEL];
__device__ float g_q    [ROWS * (size_t)D_MODEL];
__device__ float g_k    [ROWS * (size_t)D_MODEL];
__device__ float g_v    [ROWS * (size_t)D_MODEL];
__device__ float g_att  [ROWS * (size_t)D_MODEL];
__device__ float g_xres [ROWS * (size_t)D_MODEL];
__device__ float g_xn2  [ROWS * (size_t)D_MODEL];
__device__ float g_h1   [ROWS * (size_t)D_FF];
__device__ float g_h3   [ROWS * (size_t)D_FF];
__device__ float g_sc   [(size_t)BATCH * N_HEADS * SEQ * SEQ];

// ---------------------------------------------------------------------------
// Async-copy + TF32 helpers
// ---------------------------------------------------------------------------
__device__ __forceinline__ void cp_async16(void* smem, const void* gmem) {
    unsigned s = (unsigned)__cvta_generic_to_shared(smem);
    asm volatile("cp.async.cg.shared.global [%0], [%1], 16;\n" :: "r"(s), "l"(gmem));
}
__device__ __forceinline__ void cp_commit() {
    asm volatile("cp.async.commit_group;\n");
}
template <int N>
__device__ __forceinline__ void cp_wait() {
    asm volatile("cp.async.wait_group %0;\n" :: "n"(N));
}

__device__ __forceinline__ void split_tf32(float x, unsigned& hi, unsigned& lo) {
    asm("cvt.rna.tf32.f32 %0, %1;" : "=r"(hi) : "f"(x));
    float r = x - __uint_as_float(hi);
    asm("cvt.rna.tf32.f32 %0, %1;" : "=r"(lo) : "f"(r));
}
__device__ __forceinline__ void split_tf32_f(float x, float& hi, float& lo) {
    unsigned uh, ul;
    split_tf32(x, uh, ul);
    hi = __uint_as_float(uh);
    lo = __uint_as_float(ul);
}

__device__ __forceinline__ void mma_tf32(float* c, const unsigned* a, const unsigned* b) {
    asm volatile(
        "mma.sync.aligned.m16n8k8.row.col.f32.tf32.tf32.f32 "
        "{%0,%1,%2,%3}, {%4,%5,%6,%7}, {%8,%9}, {%0,%1,%2,%3};\n"
        : "+f"(c[0]), "+f"(c[1]), "+f"(c[2]), "+f"(c[3])
        : "r"(a[0]), "r"(a[1]), "r"(a[2]), "r"(a[3]),
          "r"(b[0]), "r"(b[1]));
}

// ---------------------------------------------------------------------------
// 3xTF32 tensor-core GEMM with cp.async double buffering and a shared
// B-split pass (B is split to tf32 hi/lo ONCE per tile instead of redundantly
// by every warp in the inner loop).
//   C = A * op(B) (+ aux)
//   A: [M,K] row-major (lda)
//   BT=true : B is [N,K] row-major (NT: weights / K^T)
//   BT=false: B is [K,N] row-major (NN: attn*V)
//   Batched via blockIdx.z = (zb*16 + zh) with per-(b,h) strides.
//   CAUSAL: skip tiles entirely above the diagonal.
// Tiles: BM=128, BN=64, BK=16. 8 warps in 4(m) x 2(n); 32x32 per warp.
// ---------------------------------------------------------------------------
constexpr int BM = 128, BN = 64, BK = 16, GEMM_THREADS = 256;
constexpr int AST  = BK + 4;   // A / B-NT row stride (20) -> conflict-free frag LDS
constexpr int BNST = BN + 4;   // B-NN row stride (68)    -> conflict-free frag LDS

template <bool BT, bool ADD_AUX, bool CAUSAL>
__global__ __launch_bounds__(GEMM_THREADS, 2)
void gemm_kernel(const float* __restrict__ A, const float* __restrict__ B,
                 float* __restrict__ C, const float* __restrict__ aux,
                 int M, int N, int K, int lda, int ldb, int ldc,
                 long asb, long ash, long bsb, long bsh, long csb, long csh)
{
    if (CAUSAL && (int)blockIdx.x * BN > (int)blockIdx.y * BM + (BM - 1)) return;

    const int zb = blockIdx.z >> 4;
    const int zh = blockIdx.z & 15;
    A += zb * asb + zh * ash;
    B += zb * bsb + zh * bsh;
    C += zb * csb + zh * csh;

    const int m0  = blockIdx.y * BM;
    const int n0  = blockIdx.x * BN;
    const int tid = threadIdx.x;
    const int warp = tid >> 5;
    const int lane = tid & 31;
    const int g    = lane >> 2;       // groupID 0..7
    const int tig  = lane & 3;        // thread-in-group 0..3
    const int warp_m = warp >> 1;     // 0..3
    const int warp_n = warp & 1;      // 0..1

    constexpr int BSZ = BT ? BN * AST : BK * BNST;
    __shared__ float As [2][BM * AST];   // raw fp32 A (split in-loop, 2x redundant only)
    __shared__ float Brw[2][BSZ];        // raw fp32 B (cp.async dst)
    __shared__ float BsH[BSZ];           // B tf32-hi (split once per tile)
    __shared__ float BsL[BSZ];           // B tf32-lo

    float acc[2][4][4];
    #pragma unroll
    for (int mt = 0; mt < 2; mt++)
        #pragma unroll
        for (int nt = 0; nt < 4; nt++)
            #pragma unroll
            for (int r = 0; r < 4; r++) acc[mt][nt][r] = 0.0f;

    auto load_tile = [&](int k0, int buf) {
        #pragma unroll
        for (int h = 0; h < 2; h++) {
            const int f   = tid + h * 256;        // 0..511
            const int row = f >> 2;               // 0..127
            const int cg  = (f & 3) * 4;          // 0,4,8,12
            cp_async16(&As[buf][row * AST + cg],
                       A + (long)(m0 + row) * lda + k0 + cg);
        }
        if (BT) {
            const int row = tid >> 2;             // 0..63
            const int cg  = (tid & 3) * 4;
            cp_async16(&Brw[buf][row * AST + cg],
                       B + (long)(n0 + row) * ldb + k0 + cg);
        } else {
            const int row = tid >> 4;             // 0..15
            const int cg  = (tid & 15) * 4;       // 0..60
            cp_async16(&Brw[buf][row * BNST + cg],
                       B + (long)(k0 + row) * ldb + n0 + cg);
        }
    };

    // Split the 64x16 (or 16x64) raw B tile into hi/lo once per tile.
    auto split_B = [&](int buf) {
        const float* __restrict__ src = Brw[buf];
        #pragma unroll
        for (int e = 0; e < 4; e++) {
            const int idx = tid * 4 + e;          // 0..1023
            int off;
            if (BT) off = (idx >> 4) * AST  + (idx & 15);
            else    off = (idx >> 6) * BNST + (idx & 63);
            float hi, lo;
            split_tf32_f(src[off], hi, lo);
            BsH[off] = hi;
            BsL[off] = lo;
        }
    };

    auto compute_tile = [&](int buf) {
        const float* __restrict__ ap = As[buf];
        #pragma unroll
        for (int k8 = 0; k8 < BK; k8 += 8) {
            const int kA = k8 + tig;
            unsigned ah[2][4], al[2][4], bh[4][2], bl[4][2];
            #pragma unroll
            for (int mt = 0; mt < 2; mt++) {
                const int m = warp_m * 32 + mt * 16 + g;
                split_tf32(ap[m * AST + kA],           ah[mt][0], al[mt][0]);
                split_tf32(ap[(m + 8) * AST + kA],     ah[mt][1], al[mt][1]);
                split_tf32(ap[m * AST + kA + 4],       ah[mt][2], al[mt][2]);
                split_tf32(ap[(m + 8) * AST + kA + 4], ah[mt][3], al[mt][3]);
            }
            #pragma unroll
            for (int nt = 0; nt < 4; nt++) {
                const int n = warp_n * 32 + nt * 8 + g;
                int o0, o1;
                if (BT) { o0 = n * AST + kA;   o1 = n * AST + kA + 4; }
                else    { o0 = kA * BNST + n;  o1 = (kA + 4) * BNST + n; }
                bh[nt][0] = __float_as_uint(BsH[o0]);
                bh[nt][1] = __float_as_uint(BsH[o1]);
                bl[nt][0] = __float_as_uint(BsL[o0]);
                bl[nt][1] = __float_as_uint(BsL[o1]);
            }
            #pragma unroll
            for (int mt = 0; mt < 2; mt++)
                #pragma unroll
                for (int nt = 0; nt < 4; nt++) {
                    mma_tf32(acc[mt][nt], ah[mt], bh[nt]);   // hi*hi
                    mma_tf32(acc[mt][nt], ah[mt], bl[nt]);   // hi*lo
                    mma_tf32(acc[mt][nt], al[mt], bh[nt]);   // lo*hi
                }
        }
    };

    // --- 2-stage cp.async pipeline with per-tile B split pass
    const int KT = K / BK;
    load_tile(0, 0);
    cp_commit();
    for (int kt = 0; kt < KT; kt++) {
        if (kt + 1 < KT) {
            load_tile((kt + 1) * BK, (kt + 1) & 1);
            cp_commit();
            cp_wait<1>();
        } else {
            cp_wait<0>();
        }
        __syncthreads();          // raw tiles for kt visible
        split_B(kt & 1);
        __syncthreads();          // BsH/BsL ready
        compute_tile(kt & 1);
        __syncthreads();          // protect raw bufs + BsH/BsL for next iter
    }

    // --- epilogue
    #pragma unroll
    for (int mt = 0; mt < 2; mt++) {
        #pragma unroll
        for (int nt = 0; nt < 4; nt++) {
            const int col = n0 + warp_n * 32 + nt * 8 + tig * 2;
            #pragma unroll
            for (int half = 0; half < 2; half++) {
                const long row = m0 + warp_m * 32 + mt * 16 + g + half * 8;
                const long off = row * ldc + col;
                float v0 = acc[mt][nt][half * 2 + 0];
                float v1 = acc[mt][nt][half * 2 + 1];
                if (ADD_AUX) { v0 += aux[off]; v1 += aux[off + 1]; }
                C[off]     = v0;
                C[off + 1] = v1;
            }
        }
    }
}

// ---------------------------------------------------------------------------
// RMSNorm: one block per token row
// ---------------------------------------------------------------------------
__global__ void rmsnorm_kernel(const float* __restrict__ x,
                               const float* __restrict__ g,
                               float* __restrict__ out)
{
    __shared__ float red[256];
    const long row  = blockIdx.x;
    const float* xr = x + row * D_MODEL;
    float* orow     = out + row * D_MODEL;
    const int tid   = threadIdx.x;

    float s = 0.0f;
    for (int i = tid; i < D_MODEL; i += 256) {
        float v = xr[i];
        s += v * v;
    }
    red[tid] = s;
    __syncthreads();
    for (int st = 128; st > 0; st >>= 1) {
        if (tid < st) red[tid] += red[tid + st];
        __syncthreads();
    }
    const float ms = red[0] * (1.0f / D_MODEL);
    const float r  = rsqrtf(ms + 1e-5f);
    for (int i = tid; i < D_MODEL; i += 256)
        orow[i] = xr[i] * r * g[i];
}

// ---------------------------------------------------------------------------
// RoPE in-place on q and k
// ---------------------------------------------------------------------------
__global__ void rope_kernel(float* __restrict__ q, float* __restrict__ k)
{
    const int p = blockIdx.x * blockDim.x + threadIdx.x;
    if (p >= ROWS * (D_MODEL / 2)) return;
    const int row = p >> 10;
    const int cp  = p & 1023;
    const int h   = cp >> 6;
    const int kk  = cp & 63;
    const int s   = row & (SEQ - 1);

    const float freq = powf(10000.0f, -(float)kk * (1.0f / 64.0f));
    const float ph   = (float)s * freq;
    float sn, cs;
    sincosf(ph, &sn, &cs);

    const long off = (long)row * D_MODEL + h * D_KH + 2 * kk;
    float e = q[off], o = q[off + 1];
    q[off]     = e * cs - o * sn;
    q[off + 1] = e * sn + o * cs;
    e = k[off]; o = k[off + 1];
    k[off]     = e * cs - o * sn;
    k[off + 1] = e * sn + o * cs;
}

// ---------------------------------------------------------------------------
// Causal softmax in place; zeros the j>i tail so PV reads dense rows.
// ---------------------------------------------------------------------------
__global__ void softmax_kernel(float* __restrict__ scores)
{
    __shared__ float red[256];
    const long  rowid = blockIdx.x;
    const long  z     = rowid >> 11;
    const int   i     = (int)(rowid & (SEQ - 1));
    float* p          = scores + z * (long)SEQ * SEQ + (long)i * SEQ;
    const int n       = i + 1;
    const int tid     = threadIdx.x;
    const float scale = 0.08838834764831845f;  // 1/sqrt(128)

    float vals[8];
    int cnt = 0;
    float m = -INFINITY;
    for (int j = tid; j < n; j += 256) {
        const float v = p[j] * scale;
        vals[cnt++] = v;
        m = fmaxf(m, v);
    }
    red[tid] = m;
    __syncthreads();
    for (int st = 128; st > 0; st >>= 1) {
        if (tid < st) red[tid] = fmaxf(red[tid], red[tid + st]);
        __syncthreads();
    }
    m = red[0];
    __syncthreads();

    float s = 0.0f;
    for (int c = 0; c < cnt; c++) {
        const float e = __expf(vals[c] - m);
        vals[c] = e;
        s += e;
    }
    red[tid] = s;
    __syncthreads();
    for (int st = 128; st > 0; st >>= 1) {
        if (tid < st) red[tid] += red[tid + st];
        __syncthreads();
    }
    const float inv = 1.0f / red[0];

    cnt = 0;
    for (int j = tid; j < n; j += 256) p[j] = vals[cnt++] * inv;
    for (int j = n + tid; j < SEQ; j += 256) p[j] = 0.0f;
}

// ---------------------------------------------------------------------------
// SwiGLU elementwise
// ---------------------------------------------------------------------------
__global__ void swiglu_kernel(float* __restrict__ a, const float* __restrict__ b, long n)
{
    const long i = (long)blockIdx.x * blockDim.x + threadIdx.x;
    if (i >= n) return;
    const float w1 = a[i];
    const float sig = 1.0f / (1.0f + __expf(-w1));
    a[i] = w1 * sig * b[i];
}

// ---------------------------------------------------------------------------
// Launch orchestration
// ---------------------------------------------------------------------------
extern "C" void kernel_launch(void* const* d_in, const int* in_sizes, int n_in,
                              void* d_out, int out_size)
{
    const float* x  = (const float*)d_in[0];
    const float* Wq = (const float*)d_in[1];
    const float* Wk = (const float*)d_in[2];
    const float* Wv = (const float*)d_in[3];
    const float* Wo = (const float*)d_in[4];
    const float* W1 = (const float*)d_in[5];
    const float* W2 = (const float*)d_in[6];
    const float* W3 = (const float*)d_in[7];
    const float* g1 = (const float*)d_in[8];
    const float* g2 = (const float*)d_in[9];
    float* out = (float*)d_out;

    float *xn, *q, *k, *v, *att, *xres, *xn2, *h1, *h3, *sc;
    cudaGetSymbolAddress((void**)&xn,   g_xn);
    cudaGetSymbolAddress((void**)&q,    g_q);
    cudaGetSymbolAddress((void**)&k,    g_k);
    cudaGetSymbolAddress((void**)&v,    g_v);
    cudaGetSymbolAddress((void**)&att,  g_att);
    cudaGetSymbolAddress((void**)&xres, g_xres);
    cudaGetSymbolAddress((void**)&xn2,  g_xn2);
    cudaGetSymbolAddress((void**)&h1,   g_h1);
    cudaGetSymbolAddress((void**)&h3,   g_h3);
    cudaGetSymbolAddress((void**)&sc,   g_sc);

    const long SD = (long)SEQ * D_MODEL;
    const long SS = (long)SEQ * SEQ;

    // 1. xn = rmsnorm(x, g1)
    rmsnorm_kernel<<<ROWS, 256>>>(x, g1, xn);

    // 2-4. q/k/v projections (NT)
    dim3 gProj(D_MODEL / BN, ROWS / BM, 1);
    gemm_kernel<true, false, false><<<gProj, GEMM_THREADS>>>(
        xn, Wq, q, nullptr, ROWS, D_MODEL, D_MODEL, D_MODEL, D_MODEL, D_MODEL,
        0, 0, 0, 0, 0, 0);
    gemm_kernel<true, false, false><<<gProj, GEMM_THREADS>>>(
        xn, Wk, k, nullptr, ROWS, D_MODEL, D_MODEL, D_MODEL, D_MODEL, D_MODEL,
        0, 0, 0, 0, 0, 0);
    gemm_kernel<true, false, false><<<gProj, GEMM_THREADS>>>(
        xn, Wv, v, nullptr, ROWS, D_MODEL, D_MODEL, D_MODEL, D_MODEL, D_MODEL,
        0, 0, 0, 0, 0, 0);

    // 5. RoPE on q,k
    rope_kernel<<<(ROWS * (D_MODEL / 2) + 255) / 256, 256>>>(q, k);

    // 6. scores = q @ k^T (batched, causal tile skip)
    dim3 gScores(SEQ / BN, SEQ / BM, BATCH * N_HEADS);
    gemm_kernel<true, false, true><<<gScores, GEMM_THREADS>>>(
        q, k, sc, nullptr, SEQ, SEQ, D_KH, D_MODEL, D_MODEL, SEQ,
        SD, D_KH, SD, D_KH, (long)N_HEADS * SS, SS);

    // 7. causal softmax in place
    softmax_kernel<<<BATCH * N_HEADS * SEQ, 256>>>(sc);

    // 8. att = attn @ v (NN, batched) -> [b,s,h*128+d]
    dim3 gPV(D_KH / BN, SEQ / BM, BATCH * N_HEADS);
    gemm_kernel<false, false, false><<<gPV, GEMM_THREADS>>>(
        sc, v, att, nullptr, SEQ, D_KH, SEQ, SEQ, D_MODEL, D_MODEL,
        (long)N_HEADS * SS, SS, SD, D_KH, SD, D_KH);

    // 9. xres = att @ Wo^T + x
    gemm_kernel<true, true, false><<<gProj, GEMM_THREADS>>>(
        att, Wo, xres, x, ROWS, D_MODEL, D_MODEL, D_MODEL, D_MODEL, D_MODEL,
        0, 0, 0, 0, 0, 0);

    // 10. xn2 = rmsnorm(xres, g2)
    rmsnorm_kernel<<<ROWS, 256>>>(xres, g2, xn2);

    // 11-12. h1 = xn2 @ W1^T, h3 = xn2 @ W3^T
    dim3 gFF(D_FF / BN, ROWS / BM, 1);
    gemm_kernel<true, false, false><<<gFF, GEMM_THREADS>>>(
        xn2, W1, h1, nullptr, ROWS, D_FF, D_MODEL, D_MODEL, D_MODEL, D_FF,
        0, 0, 0, 0, 0, 0);
    gemm_kernel<true, false, false><<<gFF, GEMM_THREADS>>>(
        xn2, W3, h3, nullptr, ROWS, D_FF, D_MODEL, D_MODEL, D_MODEL, D_FF,
        0, 0, 0, 0, 0, 0);

    // 13. h1 = silu(h1) * h3
    const long nh = (long)ROWS * D_FF;
    swiglu_kernel<<<(int)((nh + 255) / 256), 256>>>(h1, h3, nh);

    // 14. out = h1 @ W2^T + xres
    gemm_kernel<true, true, false><<<gProj, GEMM_THREADS>>>(
        h1, W2, out, xres, ROWS, D_MODEL, D_FF, D_FF, D_FF, D_MODEL,
        0, 0, 0, 0, 0, 0);
}

// round 8
// speedup vs baseline: 1.4830x; 1.4830x over previous
#include <cuda_runtime.h>
#include <math.h>
#include <stdint.h>

// ---------------------------------------------------------------------------
// Problem constants
// ---------------------------------------------------------------------------
#define D_MODEL 2048
#define N_HEADS 16
#define D_KH    128
#define D_FF    5504
#define BATCH   2
#define SEQ     2048
#define ROWS    (BATCH * SEQ)

// ---------------------------------------------------------------------------
// Scratch (device globals: allocation-free, capture-safe)
// ---------------------------------------------------------------------------
__device__ float g_xn   [ROWS * (size_t)D_MODEL];
__device__ float g_q    [ROWS * (size_t)D_MODEL];
__device__ float g_k    [ROWS * (size_t)D_MODEL];
__device__ float g_v    [ROWS * (size_t)D_MODEL];
__device__ float g_att  [ROWS * (size_t)D_MODEL];
__device__ float g_xres [ROWS * (size_t)D_MODEL];
__device__ float g_xn2  [ROWS * (size_t)D_MODEL];
__device__ float g_h1   [ROWS * (size_t)D_FF];
__device__ float g_h3   [ROWS * (size_t)D_FF];
__device__ float g_sc   [(size_t)BATCH * N_HEADS * SEQ * SEQ];

// ---------------------------------------------------------------------------
// BF16 split helpers
//   x = hi + lo with hi,lo bf16  ->  ~16 mantissa bits captured.
//   pack_split packs the k-even/k-odd pair into bf16x2 words (low half = even k).
// ---------------------------------------------------------------------------
__device__ __forceinline__ void pack_split(float x0, float x1,
                                           uint32_t& whi, uint32_t& wlo) {
    asm("cvt.rn.bf16x2.f32 %0, %1, %2;" : "=r"(whi) : "f"(x1), "f"(x0));
    // bf16 -> f32 is exact: just place the 16 bits in the high half.
    float h0 = __uint_as_float(whi << 16);
    float h1 = __uint_as_float(whi & 0xffff0000u);
    float l0 = x0 - h0;
    float l1 = x1 - h1;
    asm("cvt.rn.bf16x2.f32 %0, %1, %2;" : "=r"(wlo) : "f"(l1), "f"(l0));
}

__device__ __forceinline__ void mma_bf16(float* c, const uint32_t* a, const uint32_t* b) {
    asm volatile(
        "mma.sync.aligned.m16n8k16.row.col.f32.bf16.bf16.f32 "
        "{%0,%1,%2,%3}, {%4,%5,%6,%7}, {%8,%9}, {%0,%1,%2,%3};\n"
        : "+f"(c[0]), "+f"(c[1]), "+f"(c[2]), "+f"(c[3])
        : "r"(a[0]), "r"(a[1]), "r"(a[2]), "r"(a[3]),
          "r"(b[0]), "r"(b[1]));
}

// ---------------------------------------------------------------------------
// 3xBF16-split tensor-core GEMM (m16n8k16), double-buffered smem holding
// PRE-SPLIT packed bf16x2 tiles. Inner loop = pure LDS + MMA (no ALU).
//   C = A * op(B) (+ aux)
//   A: [M,K] row-major (lda)
//   BT=true : B is [N,K] row-major (NT: weights / K^T)
//   BT=false: B is [K,N] row-major (NN: attn*V)
//   Batched via blockIdx.z = (zb*16 + zh). CAUSAL: skip upper-tri tiles.
// Tiles: BM=128, BN=64, BK=16 (one k16 MMA step per tile).
// 8 warps in 4(m) x 2(n); each warp 32x32.
// Smem layout: packed k-pair words, row stride 12 words (conflict-free LDS:
// banks (g*12+tig) mod 32 cover all 32 banks across a warp).
// ---------------------------------------------------------------------------
constexpr int BM = 128, BN = 64, BK = 16, GEMM_THREADS = 256;
constexpr int SW = 12;                 // row stride in bf16x2 words

template <bool BT, bool ADD_AUX, bool CAUSAL>
__global__ __launch_bounds__(GEMM_THREADS, 2)
void gemm_kernel(const float* __restrict__ A, const float* __restrict__ B,
                 float* __restrict__ C, const float* __restrict__ aux,
                 int M, int N, int K, int lda, int ldb, int ldc,
                 long asb, long ash, long bsb, long bsh, long csb, long csh)
{
    if (CAUSAL && (int)blockIdx.x * BN > (int)blockIdx.y * BM + (BM - 1)) return;

    const int zb = blockIdx.z >> 4;
    const int zh = blockIdx.z & 15;
    A += zb * asb + zh * ash;
    B += zb * bsb + zh * bsh;
    C += zb * csb + zh * csh;

    const int m0  = blockIdx.y * BM;
    const int n0  = blockIdx.x * BN;
    const int tid = threadIdx.x;
    const int warp = tid >> 5;
    const int lane = tid & 31;
    const int g    = lane >> 2;       // groupID 0..7
    const int tig  = lane & 3;        // thread-in-group 0..3
    const int warp_m = warp >> 1;     // 0..3
    const int warp_n = warp & 1;      // 0..1

    __shared__ uint32_t AsH[2][BM * SW];
    __shared__ uint32_t AsL[2][BM * SW];
    __shared__ uint32_t BsH[2][BN * SW];
    __shared__ uint32_t BsL[2][BN * SW];

    float acc[2][4][4];
    #pragma unroll
    for (int mt = 0; mt < 2; mt++)
        #pragma unroll
        for (int nt = 0; nt < 4; nt++)
            #pragma unroll
            for (int r = 0; r < 4; r++) acc[mt][nt][r] = 0.0f;

    // ---- prefetch registers
    float4 aR0, aR1;                        // A: row (tid>>1), k (tid&1)*8..+7
    float4 bR;                              // B NT: row (tid>>2), k (tid&3)*4..+3
    float bnn0, bnn1, bnn2, bnn3;           // B NN: col (tid&63), k-pairs (tid>>6), +4

    const int aRow = tid >> 1;
    const int aKb  = (tid & 1) * 8;
    const int bRowNT = tid >> 2;
    const int bKbNT  = (tid & 3) * 4;
    const int nNN    = tid & 63;
    const int kpNN   = tid >> 6;            // 0..3

    auto load_tile = [&](int k0) {
        const float* ap = A + (long)(m0 + aRow) * lda + k0 + aKb;
        aR0 = *(const float4*)(ap);
        aR1 = *(const float4*)(ap + 4);
        if (BT) {
            bR = *(const float4*)(B + (long)(n0 + bRowNT) * ldb + k0 + bKbNT);
        } else {
            const long col = n0 + nNN;
            bnn0 = B[(long)(k0 + 2 * kpNN    ) * ldb + col];
            bnn1 = B[(long)(k0 + 2 * kpNN + 1) * ldb + col];
            bnn2 = B[(long)(k0 + 2 * (kpNN+4)    ) * ldb + col];
            bnn3 = B[(long)(k0 + 2 * (kpNN+4) + 1) * ldb + col];
        }
    };

    auto store_tile = [&](int buf) {
        uint32_t h[4], l[4];
        pack_split(aR0.x, aR0.y, h[0], l[0]);
        pack_split(aR0.z, aR0.w, h[1], l[1]);
        pack_split(aR1.x, aR1.y, h[2], l[2]);
        pack_split(aR1.z, aR1.w, h[3], l[3]);
        const int adst = aRow * SW + (tid & 1) * 4;
        *(uint4*)&AsH[buf][adst] = make_uint4(h[0], h[1], h[2], h[3]);
        *(uint4*)&AsL[buf][adst] = make_uint4(l[0], l[1], l[2], l[3]);
        if (BT) {
            uint32_t bh0, bl0, bh1, bl1;
            pack_split(bR.x, bR.y, bh0, bl0);
            pack_split(bR.z, bR.w, bh1, bl1);
            const int bdst = bRowNT * SW + (tid & 3) * 2;
            *(uint2*)&BsH[buf][bdst] = make_uint2(bh0, bh1);
            *(uint2*)&BsL[buf][bdst] = make_uint2(bl0, bl1);
        } else {
            uint32_t bh0, bl0, bh1, bl1;
            pack_split(bnn0, bnn1, bh0, bl0);
            pack_split(bnn2, bnn3, bh1, bl1);
            BsH[buf][nNN * SW + kpNN]     = bh0;
            BsL[buf][nNN * SW + kpNN]     = bl0;
            BsH[buf][nNN * SW + kpNN + 4] = bh1;
            BsL[buf][nNN * SW + kpNN + 4] = bl1;
        }
    };

    auto compute_tile = [&](int buf) {
        const uint32_t* __restrict__ ah = AsH[buf];
        const uint32_t* __restrict__ al = AsL[buf];
        const uint32_t* __restrict__ bhp = BsH[buf];
        const uint32_t* __restrict__ blp = BsL[buf];

        uint32_t aH[2][4], aL[2][4], bH[4][2], bL[4][2];
        #pragma unroll
        for (int mt = 0; mt < 2; mt++) {
            const int m = warp_m * 32 + mt * 16 + g;
            aH[mt][0] = ah[m * SW + tig];
            aH[mt][1] = ah[(m + 8) * SW + tig];
            aH[mt][2] = ah[m * SW + tig + 4];
            aH[mt][3] = ah[(m + 8) * SW + tig + 4];
            aL[mt][0] = al[m * SW + tig];
            aL[mt][1] = al[(m + 8) * SW + tig];
            aL[mt][2] = al[m * SW + tig + 4];
            aL[mt][3] = al[(m + 8) * SW + tig + 4];
        }
        #pragma unroll
        for (int nt = 0; nt < 4; nt++) {
            const int n = warp_n * 32 + nt * 8 + g;
            bH[nt][0] = bhp[n * SW + tig];
            bH[nt][1] = bhp[n * SW + tig + 4];
            bL[nt][0] = blp[n * SW + tig];
            bL[nt][1] = blp[n * SW + tig + 4];
        }
        #pragma unroll
        for (int mt = 0; mt < 2; mt++)
            #pragma unroll
            for (int nt = 0; nt < 4; nt++) {
                mma_bf16(acc[mt][nt], aH[mt], bH[nt]);   // hi*hi
                mma_bf16(acc[mt][nt], aH[mt], bL[nt]);   // hi*lo
                mma_bf16(acc[mt][nt], aL[mt], bH[nt]);   // lo*hi
            }
    };

    // ---- pipeline: LDG(kt+1) overlaps compute(kt); one sync per tile
    const int KT = K / BK;
    load_tile(0);
    store_tile(0);
    __syncthreads();
    for (int kt = 0; kt < KT; kt++) {
        const bool more = (kt + 1 < KT);
        if (more) load_tile((kt + 1) * BK);
        compute_tile(kt & 1);
        if (more) {
            store_tile((kt + 1) & 1);
            __syncthreads();
        }
    }

    // ---- epilogue (c0,c1: row g cols 2tig..+1; c2,c3: row g+8)
    #pragma unroll
    for (int mt = 0; mt < 2; mt++) {
        #pragma unroll
        for (int nt = 0; nt < 4; nt++) {
            const int col = n0 + warp_n * 32 + nt * 8 + tig * 2;
            #pragma unroll
            for (int half = 0; half < 2; half++) {
                const long row = m0 + warp_m * 32 + mt * 16 + g + half * 8;
                const long off = row * ldc + col;
                float v0 = acc[mt][nt][half * 2 + 0];
                float v1 = acc[mt][nt][half * 2 + 1];
                if (ADD_AUX) { v0 += aux[off]; v1 += aux[off + 1]; }
                C[off]     = v0;
                C[off + 1] = v1;
            }
        }
    }
}

// ---------------------------------------------------------------------------
// RMSNorm: one block per token row
// ---------------------------------------------------------------------------
__global__ void rmsnorm_kernel(const float* __restrict__ x,
                               const float* __restrict__ g,
                               float* __restrict__ out)
{
    __shared__ float red[256];
    const long row  = blockIdx.x;
    const float* xr = x + row * D_MODEL;
    float* orow     = out + row * D_MODEL;
    const int tid   = threadIdx.x;

    float s = 0.0f;
    for (int i = tid; i < D_MODEL; i += 256) {
        float v = xr[i];
        s += v * v;
    }
    red[tid] = s;
    __syncthreads();
    for (int st = 128; st > 0; st >>= 1) {
        if (tid < st) red[tid] += red[tid + st];
        __syncthreads();
    }
    const float ms = red[0] * (1.0f / D_MODEL);
    const float r  = rsqrtf(ms + 1e-5f);
    for (int i = tid; i < D_MODEL; i += 256)
        orow[i] = xr[i] * r * g[i];
}

// ---------------------------------------------------------------------------
// RoPE in-place on q and k. The softmax scale 1/sqrt(D_KH) is folded into
// q's rotation (scores then need no extra scaling).
// ---------------------------------------------------------------------------
__global__ void rope_kernel(float* __restrict__ q, float* __restrict__ k)
{
    const int p = blockIdx.x * blockDim.x + threadIdx.x;
    if (p >= ROWS * (D_MODEL / 2)) return;
    const int row = p >> 10;
    const int cp  = p & 1023;
    const int h   = cp >> 6;
    const int kk  = cp & 63;
    const int s   = row & (SEQ - 1);

    const float freq = powf(10000.0f, -(float)kk * (1.0f / 64.0f));
    const float ph   = (float)s * freq;
    float sn, cs;
    sincosf(ph, &sn, &cs);
    const float scale = 0.08838834764831845f;  // 1/sqrt(128)
    const float csq = cs * scale, snq = sn * scale;

    const long off = (long)row * D_MODEL + h * D_KH + 2 * kk;
    float e = q[off], o = q[off + 1];
    q[off]     = e * csq - o * snq;
    q[off + 1] = e * snq + o * csq;
    e = k[off]; o = k[off + 1];
    k[off]     = e * cs - o * sn;
    k[off + 1] = e * sn + o * cs;
}

// ---------------------------------------------------------------------------
// Causal softmax in place (scores already pre-scaled via q).
// Zeros the j>i tail so PV reads dense rows.
// ---------------------------------------------------------------------------
__global__ void softmax_kernel(float* __restrict__ scores)
{
    __shared__ float red[256];
    const long  rowid = blockIdx.x;
    const long  z     = rowid >> 11;
    const int   i     = (int)(rowid & (SEQ - 1));
    float* p          = scores + z * (long)SEQ * SEQ + (long)i * SEQ;
    const int n       = i + 1;
    const int tid     = threadIdx.x;

    float vals[8];
    int cnt = 0;
    float m = -INFINITY;
    for (int j = tid; j < n; j += 256) {
        const float v = p[j];
        vals[cnt++] = v;
        m = fmaxf(m, v);
    }
    red[tid] = m;
    __syncthreads();
    for (int st = 128; st > 0; st >>= 1) {
        if (tid < st) red[tid] = fmaxf(red[tid], red[tid + st]);
        __syncthreads();
    }
    m = red[0];
    __syncthreads();

    float s = 0.0f;
    for (int c = 0; c < cnt; c++) {
        const float e = __expf(vals[c] - m);
        vals[c] = e;
        s += e;
    }
    red[tid] = s;
    __syncthreads();
    for (int st = 128; st > 0; st >>= 1) {
        if (tid < st) red[tid] += red[tid + st];
        __syncthreads();
    }
    const float inv = 1.0f / red[0];

    cnt = 0;
    for (int j = tid; j < n; j += 256) p[j] = vals[cnt++] * inv;
    for (int j = n + tid; j < SEQ; j += 256) p[j] = 0.0f;
}

// ---------------------------------------------------------------------------
// SwiGLU elementwise
// ---------------------------------------------------------------------------
__global__ void swiglu_kernel(float* __restrict__ a, const float* __restrict__ b, long n)
{
    const long i = (long)blockIdx.x * blockDim.x + threadIdx.x;
    if (i >= n) return;
    const float w1 = a[i];
    const float sig = 1.0f / (1.0f + __expf(-w1));
    a[i] = w1 * sig * b[i];
}

// ---------------------------------------------------------------------------
// Launch orchestration
// ---------------------------------------------------------------------------
extern "C" void kernel_launch(void* const* d_in, const int* in_sizes, int n_in,
                              void* d_out, int out_size)
{
    const float* x  = (const float*)d_in[0];
    const float* Wq = (const float*)d_in[1];
    const float* Wk = (const float*)d_in[2];
    const float* Wv = (const float*)d_in[3];
    const float* Wo = (const float*)d_in[4];
    const float* W1 = (const float*)d_in[5];
    const float* W2 = (const float*)d_in[6];
    const float* W3 = (const float*)d_in[7];
    const float* g1 = (const float*)d_in[8];
    const float* g2 = (const float*)d_in[9];
    float* out = (float*)d_out;

    float *xn, *q, *k, *v, *att, *xres, *xn2, *h1, *h3, *sc;
    cudaGetSymbolAddress((void**)&xn,   g_xn);
    cudaGetSymbolAddress((void**)&q,    g_q);
    cudaGetSymbolAddress((void**)&k,    g_k);
    cudaGetSymbolAddress((void**)&v,    g_v);
    cudaGetSymbolAddress((void**)&att,  g_att);
    cudaGetSymbolAddress((void**)&xres, g_xres);
    cudaGetSymbolAddress((void**)&xn2,  g_xn2);
    cudaGetSymbolAddress((void**)&h1,   g_h1);
    cudaGetSymbolAddress((void**)&h3,   g_h3);
    cudaGetSymbolAddress((void**)&sc,   g_sc);

    const long SD = (long)SEQ * D_MODEL;
    const long SS = (long)SEQ * SEQ;

    // 1. xn = rmsnorm(x, g1)
    rmsnorm_kernel<<<ROWS, 256>>>(x, g1, xn);

    // 2-4. q/k/v projections (NT)
    dim3 gProj(D_MODEL / BN, ROWS / BM, 1);
    gemm_kernel<true, false, false><<<gProj, GEMM_THREADS>>>(
        xn, Wq, q, nullptr, ROWS, D_MODEL, D_MODEL, D_MODEL, D_MODEL, D_MODEL,
        0, 0, 0, 0, 0, 0);
    gemm_kernel<true, false, false><<<gProj, GEMM_THREADS>>>(
        xn, Wk, k, nullptr, ROWS, D_MODEL, D_MODEL, D_MODEL, D_MODEL, D_MODEL,
        0, 0, 0, 0, 0, 0);
    gemm_kernel<true, false, false><<<gProj, GEMM_THREADS>>>(
        xn, Wv, v, nullptr, ROWS, D_MODEL, D_MODEL, D_MODEL, D_MODEL, D_MODEL,
        0, 0, 0, 0, 0, 0);

    // 5. RoPE on q,k (folds softmax scale into q)
    rope_kernel<<<(ROWS * (D_MODEL / 2) + 255) / 256, 256>>>(q, k);

    // 6. scores = q @ k^T (batched, causal tile skip)
    dim3 gScores(SEQ / BN, SEQ / BM, BATCH * N_HEADS);
    gemm_kernel<true, false, true><<<gScores, GEMM_THREADS>>>(
        q, k, sc, nullptr, SEQ, SEQ, D_KH, D_MODEL, D_MODEL, SEQ,
        SD, D_KH, SD, D_KH, (long)N_HEADS * SS, SS);

    // 7. causal softmax in place
    softmax_kernel<<<BATCH * N_HEADS * SEQ, 256>>>(sc);

    // 8. att = attn @ v (NN, batched) -> [b,s,h*128+d]
    dim3 gPV(D_KH / BN, SEQ / BM, BATCH * N_HEADS);
    gemm_kernel<false, false, false><<<gPV, GEMM_THREADS>>>(
        sc, v, att, nullptr, SEQ, D_KH, SEQ, SEQ, D_MODEL, D_MODEL,
        (long)N_HEADS * SS, SS, SD, D_KH, SD, D_KH);

    // 9. xres = att @ Wo^T + x
    gemm_kernel<true, true, false><<<gProj, GEMM_THREADS>>>(
        att, Wo, xres, x, ROWS, D_MODEL, D_MODEL, D_MODEL, D_MODEL, D_MODEL,
        0, 0, 0, 0, 0, 0);

    // 10. xn2 = rmsnorm(xres, g2)
    rmsnorm_kernel<<<ROWS, 256>>>(xres, g2, xn2);

    // 11-12. h1 = xn2 @ W1^T, h3 = xn2 @ W3^T
    dim3 gFF(D_FF / BN, ROWS / BM, 1);
    gemm_kernel<true, false, false><<<gFF, GEMM_THREADS>>>(
        xn2, W1, h1, nullptr, ROWS, D_FF, D_MODEL, D_MODEL, D_MODEL, D_FF,
        0, 0, 0, 0, 0, 0);
    gemm_kernel<true, false, false><<<gFF, GEMM_THREADS>>>(
        xn2, W3, h3, nullptr, ROWS, D_FF, D_MODEL, D_MODEL, D_MODEL, D_FF,
        0, 0, 0, 0, 0, 0);

    // 13. h1 = silu(h1) * h3
    const long nh = (long)ROWS * D_FF;
    swiglu_kernel<<<(int)((nh + 255) / 256), 256>>>(h1, h3, nh);

    // 14. out = h1 @ W2^T + xres
    gemm_kernel<true, true, false><<<gProj, GEMM_THREADS>>>(
        h1, W2, out, xres, ROWS, D_MODEL, D_FF, D_FF, D_FF, D_MODEL,
        0, 0, 0, 0, 0, 0);
}